// round 9
// baseline (speedup 1.0000x reference)
#include <cuda_runtime.h>
#include <cstdint>

// PatchEmbedder: B=8, P=1024, D=512, BUCKETS=65536, LS=(8,7,6)
//
// Inputs identified by element count (host side):
//   33554432 -> emb tables (3, appearance order = emb_1, emb_2, emb_3)
//   8192     -> patch_mask
//   65536    -> {ids_1, mask_1}   57344 -> {ids_2, mask_2}   49152 -> {ids_3, mask_3}
// Layout (ids-vs-mask per pair, mask width u8/i32/f32, patch_mask width,
// ids stride i32/i64) detected by ONE tiny probe launch (7 warps).
//
// Main kernel: persistent CTAs, grid-stride over patches, software-pipelined
// id/mask staging (next patch's ids prefetched into registers during the
// current patch's gather) with double-buffered pointer table -> gather loads
// in flight ~continuously instead of ~60% duty cycle.

#define NPATCH (8 * 1024)
#define DV 128          // 512 floats = 128 float4 per embedding row
#define L1N 8
#define L2N 7
#define L3N 6
#define LTOT (L1N + L2N + L3N)  // 21
#define GRID 1776               // 12 CTAs/SM on 148 SMs; single persistent wave

// g_cfg: [0..2] swap_k  [3..5] ids stride (1|2)  [6..8] mask width (1|4)
//        [9] patch_mask width (1|4)
__device__ int g_cfg[10];

// 7 warps: warp c probes buffer c (0..5 = a1,b1,a2,b2,a3,b3; 6 = patch_mask).
__global__ void probe_kernel(const unsigned char* a1, const unsigned char* b1,
                             const unsigned char* a2, const unsigned char* b2,
                             const unsigned char* a3, const unsigned char* b3,
                             const unsigned char* pm)
{
    const int w = threadIdx.x >> 5;      // 0..6
    const int lane = threadIdx.x & 31;
    const unsigned char* cand[7] = {a1, b1, a2, b2, a3, b3, pm};
    const int nbytes[7] = {65536, 65536, 57344, 57344, 49152, 49152, 8192};

    __shared__ int s_isMask[7], s_odd[7], s_wide[7];

    {
        const unsigned char* p = cand[w];
        const int n = nbytes[w];
        const unsigned char bv = p[(size_t)lane * (size_t)(n / 32)];
        const unsigned wv = ((const unsigned*)p)[(size_t)lane * (size_t)((n / 4) / 32)];
        const int      ov = ((const int*)p)[2 * lane + 1];

        unsigned v = 0;
        if (bv > 1)                        v |= 1;   // byte-bool violated
        if (wv > 1u)                       v |= 2;   // word-int-bool violated
        if (wv != 0u && wv != 0x3F800000u) v |= 4;   // word-float-bool violated
        if (ov != 0)                       v |= 8;   // odd-words-zero violated
        v = __reduce_or_sync(0xFFFFFFFFu, v);

        if (lane == 0) {
            s_isMask[w] = (!(v & 2)) || (!(v & 4)) || (!(v & 1));
            s_odd[w]    = (v & 8) ? 1 : 0;
            s_wide[w]   = ((!(v & 2)) || (!(v & 4))) ? 1 : 0;
        }
    }
    __syncthreads();

    if (threadIdx.x == 0) {
        for (int k = 0; k < 3; k++) {
            const int A = 2 * k, B = 2 * k + 1;
            const int swap = (s_isMask[A] && !s_isMask[B]) ? 1 : 0;
            const int idsI = swap ? B : A;
            const int mI   = swap ? A : B;
            g_cfg[k]     = swap;
            g_cfg[3 + k] = s_odd[idsI] ? 1 : 2;   // odd words all zero => int64
            g_cfg[6 + k] = s_wide[mI] ? 4 : 1;
        }
        g_cfg[9] = s_wide[6] ? 4 : 1;
    }
}

__global__ __launch_bounds__(128, 12) void patch_embed_kernel(
    const unsigned char* __restrict__ a1, const unsigned char* __restrict__ b1,
    const unsigned char* __restrict__ a2, const unsigned char* __restrict__ b2,
    const unsigned char* __restrict__ a3, const unsigned char* __restrict__ b3,
    const unsigned char* __restrict__ pmask,
    const float4* __restrict__ e1,
    const float4* __restrict__ e2,
    const float4* __restrict__ e3,
    float4* __restrict__ out)
{
    __shared__ const float4* ptrs[2][LTOT];

    const int t = threadIdx.x;      // 0..127
    const int stride = gridDim.x;

    // ---- per-staging-thread constants (t < LTOT) ----
    const unsigned char* idsP = nullptr;
    const unsigned char* mskP = nullptr;
    const float4* ebase = nullptr;
    int nk = 1, joff = 0, st = 1, wm = 1;
    const int wp = g_cfg[9];
    if (t < LTOT) {
        int k;
        if (t < L1N)            { k = 0; nk = L1N; joff = t; }
        else if (t < L1N + L2N) { k = 1; nk = L2N; joff = t - L1N; }
        else                    { k = 2; nk = L3N; joff = t - L1N - L2N; }
        const unsigned char* pa = (k == 0) ? a1 : ((k == 1) ? a2 : a3);
        const unsigned char* pb = (k == 0) ? b1 : ((k == 1) ? b2 : b3);
        ebase = (k == 0) ? e1 : ((k == 1) ? e2 : e3);
        const int swap = g_cfg[k];
        st = g_cfg[3 + k];
        wm = g_cfg[6 + k];
        idsP = swap ? pb : pa;
        mskP = swap ? pa : pb;
    }

    // staged raw values for the *current* patch (registers)
    int sid = 0, sm = 0, spm = 0;

    int patch = blockIdx.x;
    // prologue stage for first patch
    if (t < LTOT && patch < NPATCH) {
        const int idx = patch * nk + joff;
        sid = ((const int*)idsP)[idx * st];
        sm  = (wm == 4) ? (((const int*)mskP)[idx] != 0) : (mskP[idx] != 0);
        spm = (wp == 4) ? (((const int*)pmask)[patch] != 0) : (pmask[patch] != 0);
    }

    int it = 0;
    while (patch < NPATCH) {
        const int buf = it & 1;

        // publish pointers for current patch
        if (t < LTOT) {
            const float4* p = nullptr;
            if (spm && sm)
                p = ebase + (size_t)((unsigned)sid & 0xFFFFu) * DV;
            ptrs[buf][t] = p;
        }
        __syncthreads();

        // prefetch next patch's ids/masks into registers (latency hidden
        // under the gather loop below)
        const int next = patch + stride;
        if (t < LTOT && next < NPATCH) {
            const int idx = next * nk + joff;
            sid = ((const int*)idsP)[idx * st];
            sm  = (wm == 4) ? (((const int*)mskP)[idx] != 0) : (mskP[idx] != 0);
            spm = (wp == 4) ? (((const int*)pmask)[next] != 0) : (pmask[next] != 0);
        }

        // gather + sum current patch
        float4 acc = make_float4(0.f, 0.f, 0.f, 0.f);
#pragma unroll
        for (int i = 0; i < LTOT; i++) {
            const float4* p = ptrs[buf][i];     // warp-uniform
            if (p) {
                const float4 v = __ldg(p + t);
                acc.x += v.x; acc.y += v.y; acc.z += v.z; acc.w += v.w;
            }
        }
        __stcs(&out[(size_t)patch * DV + t], acc);  // evict-first: keep L2 for rows

        patch = next;
        ++it;
    }
}

extern "C" void kernel_launch(void* const* d_in, const int* in_sizes, int n_in,
                              void* d_out, int out_size)
{
    const unsigned char *a1 = nullptr, *b1 = nullptr;
    const unsigned char *a2 = nullptr, *b2 = nullptr;
    const unsigned char *a3 = nullptr, *b3 = nullptr;
    const unsigned char *pm = nullptr;
    const float4* emb[3] = {nullptr, nullptr, nullptr};
    int ne = 0;

    for (int i = 0; i < n_in; i++) {
        const int sz = in_sizes[i];
        const unsigned char* p = (const unsigned char*)d_in[i];
        switch (sz) {
            case 33554432: if (ne < 3) emb[ne++] = (const float4*)p; break;
            case 8192:     pm = p; break;
            case 65536:    if (!a1) a1 = p; else b1 = p; break;
            case 57344:    if (!a2) a2 = p; else b2 = p; break;
            case 49152:    if (!a3) a3 = p; else b3 = p; break;
            default: break;
        }
    }

    probe_kernel<<<1, 224>>>(a1, b1, a2, b2, a3, b3, pm);
    patch_embed_kernel<<<GRID, 128>>>(a1, b1, a2, b2, a3, b3, pm,
                                      emb[0], emb[1], emb[2],
                                      (float4*)d_out);
}

// round 10
// speedup vs baseline: 1.0115x; 1.0115x over previous
#include <cuda_runtime.h>
#include <cstdint>

// PatchEmbedder: B=8, P=1024, D=512, BUCKETS=65536, LS=(8,7,6)
//
// Inputs identified by element count (host side):
//   33554432 -> emb tables (3, appearance order = emb_1, emb_2, emb_3)
//   8192     -> patch_mask
//   65536    -> {ids_1, mask_1}   57344 -> {ids_2, mask_2}   49152 -> {ids_3, mask_3}
// Layout (ids-vs-mask per pair, mask width u8/i32/f32, patch_mask width,
// ids stride i32/i64) detected by ONE tiny probe launch (7 warps).
//
// Main kernel: CTA per patch. Warp 0 COMPACTS active row pointers (ballot/
// popc) so the gather loop issues BRANCH-FREE batches of 8 unconditional
// __ldg float4 loads -> per-thread MLP ~8 instead of ~2; tail via fixed
// 4/2/1 batches. launch_bounds(128,8) = 64 regs for batch buffers.

#define NPATCH (8 * 1024)
#define DV 128          // 512 floats = 128 float4 per embedding row
#define L1N 8
#define L2N 7
#define L3N 6
#define LTOT (L1N + L2N + L3N)  // 21

// g_cfg: [0..2] swap_k  [3..5] ids stride (1|2)  [6..8] mask width (1|4)
//        [9] patch_mask width (1|4)
__device__ int g_cfg[10];

// 7 warps: warp c probes buffer c (0..5 = a1,b1,a2,b2,a3,b3; 6 = patch_mask).
__global__ void probe_kernel(const unsigned char* a1, const unsigned char* b1,
                             const unsigned char* a2, const unsigned char* b2,
                             const unsigned char* a3, const unsigned char* b3,
                             const unsigned char* pm)
{
    const int w = threadIdx.x >> 5;      // 0..6
    const int lane = threadIdx.x & 31;
    const unsigned char* cand[7] = {a1, b1, a2, b2, a3, b3, pm};
    const int nbytes[7] = {65536, 65536, 57344, 57344, 49152, 49152, 8192};

    __shared__ int s_isMask[7], s_odd[7], s_wide[7];

    {
        const unsigned char* p = cand[w];
        const int n = nbytes[w];
        const unsigned char bv = p[(size_t)lane * (size_t)(n / 32)];
        const unsigned wv = ((const unsigned*)p)[(size_t)lane * (size_t)((n / 4) / 32)];
        const int      ov = ((const int*)p)[2 * lane + 1];

        unsigned v = 0;
        if (bv > 1)                        v |= 1;   // byte-bool violated
        if (wv > 1u)                       v |= 2;   // word-int-bool violated
        if (wv != 0u && wv != 0x3F800000u) v |= 4;   // word-float-bool violated
        if (ov != 0)                       v |= 8;   // odd-words-zero violated
        v = __reduce_or_sync(0xFFFFFFFFu, v);

        if (lane == 0) {
            s_isMask[w] = (!(v & 2)) || (!(v & 4)) || (!(v & 1));
            s_odd[w]    = (v & 8) ? 1 : 0;
            s_wide[w]   = ((!(v & 2)) || (!(v & 4))) ? 1 : 0;
        }
    }
    __syncthreads();

    if (threadIdx.x == 0) {
        for (int k = 0; k < 3; k++) {
            const int A = 2 * k, B = 2 * k + 1;
            const int swap = (s_isMask[A] && !s_isMask[B]) ? 1 : 0;
            const int idsI = swap ? B : A;
            const int mI   = swap ? A : B;
            g_cfg[k]     = swap;
            g_cfg[3 + k] = s_odd[idsI] ? 1 : 2;   // odd words all zero => int64
            g_cfg[6 + k] = s_wide[mI] ? 4 : 1;
        }
        g_cfg[9] = s_wide[6] ? 4 : 1;
    }
}

__device__ __forceinline__ int read_mask(const unsigned char* m, int idx, int w) {
    return (w == 4) ? (((const int*)m)[idx] != 0) : (m[idx] != 0);
}

__global__ __launch_bounds__(128, 8) void patch_embed_kernel(
    const unsigned char* __restrict__ a1, const unsigned char* __restrict__ b1,
    const unsigned char* __restrict__ a2, const unsigned char* __restrict__ b2,
    const unsigned char* __restrict__ a3, const unsigned char* __restrict__ b3,
    const unsigned char* __restrict__ pmask,
    const float4* __restrict__ e1,
    const float4* __restrict__ e2,
    const float4* __restrict__ e3,
    float4* __restrict__ out)
{
    __shared__ const float4* ptrs[LTOT];   // COMPACTED active pointers
    __shared__ int s_n;

    const int patch = blockIdx.x;   // 0..8191
    const int t = threadIdx.x;      // 0..127

    // ---- stage + compact (warp 0) ----
    if (t < 32) {
        const float4* p = nullptr;
        if (t < LTOT && read_mask(pmask, patch, g_cfg[9])) {
            int k, j, nk;
            const unsigned char *pa, *pb;
            const float4* e;
            if (t < L1N)            { k = 0; j = t;             nk = L1N; pa = a1; pb = b1; e = e1; }
            else if (t < L1N + L2N) { k = 1; j = t - L1N;       nk = L2N; pa = a2; pb = b2; e = e2; }
            else                    { k = 2; j = t - L1N - L2N; nk = L3N; pa = a3; pb = b3; e = e3; }

            const int swap = g_cfg[k];
            const int st   = g_cfg[3 + k];
            const int wm   = g_cfg[6 + k];
            const unsigned char* ids = swap ? pb : pa;
            const unsigned char* msk = swap ? pa : pb;
            const int idx = patch * nk + j;
            if (read_mask(msk, idx, wm)) {
                const unsigned id = (unsigned)((const int*)ids)[idx * st] & 0xFFFFu;
                p = e + (size_t)id * DV;
            }
        }
        const unsigned act = __ballot_sync(0xFFFFFFFFu, p != nullptr);
        if (p) ptrs[__popc(act & ((1u << t) - 1u))] = p;
        if (t == 0) s_n = __popc(act);
    }
    __syncthreads();

    const int n = s_n;
    float4 acc = make_float4(0.f, 0.f, 0.f, 0.f);

    // ---- branch-free load batches: 8, then 4 / 2 / 1 tail ----
    int i = 0;
    for (; i + 8 <= n; i += 8) {
        float4 v0 = __ldg(ptrs[i + 0] + t);
        float4 v1 = __ldg(ptrs[i + 1] + t);
        float4 v2 = __ldg(ptrs[i + 2] + t);
        float4 v3 = __ldg(ptrs[i + 3] + t);
        float4 v4 = __ldg(ptrs[i + 4] + t);
        float4 v5 = __ldg(ptrs[i + 5] + t);
        float4 v6 = __ldg(ptrs[i + 6] + t);
        float4 v7 = __ldg(ptrs[i + 7] + t);
        acc.x += v0.x + v1.x + v2.x + v3.x + v4.x + v5.x + v6.x + v7.x;
        acc.y += v0.y + v1.y + v2.y + v3.y + v4.y + v5.y + v6.y + v7.y;
        acc.z += v0.z + v1.z + v2.z + v3.z + v4.z + v5.z + v6.z + v7.z;
        acc.w += v0.w + v1.w + v2.w + v3.w + v4.w + v5.w + v6.w + v7.w;
    }
    if (i + 4 <= n) {
        float4 v0 = __ldg(ptrs[i + 0] + t);
        float4 v1 = __ldg(ptrs[i + 1] + t);
        float4 v2 = __ldg(ptrs[i + 2] + t);
        float4 v3 = __ldg(ptrs[i + 3] + t);
        acc.x += v0.x + v1.x + v2.x + v3.x;
        acc.y += v0.y + v1.y + v2.y + v3.y;
        acc.z += v0.z + v1.z + v2.z + v3.z;
        acc.w += v0.w + v1.w + v2.w + v3.w;
        i += 4;
    }
    if (i + 2 <= n) {
        float4 v0 = __ldg(ptrs[i + 0] + t);
        float4 v1 = __ldg(ptrs[i + 1] + t);
        acc.x += v0.x + v1.x;
        acc.y += v0.y + v1.y;
        acc.z += v0.z + v1.z;
        acc.w += v0.w + v1.w;
        i += 2;
    }
    if (i < n) {
        const float4 v = __ldg(ptrs[i] + t);
        acc.x += v.x; acc.y += v.y; acc.z += v.z; acc.w += v.w;
    }

    out[(size_t)patch * DV + t] = acc;
}

extern "C" void kernel_launch(void* const* d_in, const int* in_sizes, int n_in,
                              void* d_out, int out_size)
{
    const unsigned char *a1 = nullptr, *b1 = nullptr;
    const unsigned char *a2 = nullptr, *b2 = nullptr;
    const unsigned char *a3 = nullptr, *b3 = nullptr;
    const unsigned char *pm = nullptr;
    const float4* emb[3] = {nullptr, nullptr, nullptr};
    int ne = 0;

    for (int i = 0; i < n_in; i++) {
        const int sz = in_sizes[i];
        const unsigned char* p = (const unsigned char*)d_in[i];
        switch (sz) {
            case 33554432: if (ne < 3) emb[ne++] = (const float4*)p; break;
            case 8192:     pm = p; break;
            case 65536:    if (!a1) a1 = p; else b1 = p; break;
            case 57344:    if (!a2) a2 = p; else b2 = p; break;
            case 49152:    if (!a3) a3 = p; else b3 = p; break;
            default: break;
        }
    }

    probe_kernel<<<1, 224>>>(a1, b1, a2, b2, a3, b3, pm);
    patch_embed_kernel<<<NPATCH, 128>>>(a1, b1, a2, b2, a3, b3, pm,
                                        emb[0], emb[1], emb[2],
                                        (float4*)d_out);
}

// round 11
// speedup vs baseline: 1.0894x; 1.0770x over previous
#include <cuda_runtime.h>
#include <cstdint>

// PatchEmbedder: B=8, P=1024, D=512, BUCKETS=65536, LS=(8,7,6)
//
// Inputs identified by element count (host side):
//   33554432 -> emb tables (3, appearance order = emb_1, emb_2, emb_3)
//   8192     -> patch_mask
//   65536    -> {ids_1, mask_1}   57344 -> {ids_2, mask_2}   49152 -> {ids_3, mask_3}
// Layout (ids-vs-mask per pair, mask width u8/i32/f32, patch_mask width,
// ids stride i32/i64) detected by ONE tiny probe launch (7 warps; probed
// buffers are L2-resident across graph replays -> ~launch-overhead cost).
//
// Main kernel (best-measured shape, R4): CTA per patch, 128 threads, fully
// unrolled 21-iter conditional gather of coalesced float4 rows via __ldg,
// occupancy 16 CTAs/SM. Output stored with __stcs (evict-first) so 16MB of
// dead output does not evict gather rows from L2 (duplicate-row hits).
//
// Established floor: ~87MB compulsory unique-row DRAM traffic at the random-
// 2KB-granule activate ceiling (~3.5TB/s) => ~25us. This kernel sits on it.

#define NPATCH (8 * 1024)
#define DV 128          // 512 floats = 128 float4 per embedding row
#define L1N 8
#define L2N 7
#define L3N 6
#define LTOT (L1N + L2N + L3N)  // 21

// g_cfg: [0..2] swap_k  [3..5] ids stride (1|2)  [6..8] mask width (1|4)
//        [9] patch_mask width (1|4)
__device__ int g_cfg[10];

// 7 warps: warp c probes buffer c (0..5 = a1,b1,a2,b2,a3,b3; 6 = patch_mask).
__global__ void probe_kernel(const unsigned char* a1, const unsigned char* b1,
                             const unsigned char* a2, const unsigned char* b2,
                             const unsigned char* a3, const unsigned char* b3,
                             const unsigned char* pm)
{
    const int w = threadIdx.x >> 5;      // 0..6
    const int lane = threadIdx.x & 31;
    const unsigned char* cand[7] = {a1, b1, a2, b2, a3, b3, pm};
    const int nbytes[7] = {65536, 65536, 57344, 57344, 49152, 49152, 8192};

    __shared__ int s_isMask[7], s_odd[7], s_wide[7];

    {
        const unsigned char* p = cand[w];
        const int n = nbytes[w];
        // three independent sample loads per lane
        const unsigned char bv = p[(size_t)lane * (size_t)(n / 32)];
        const unsigned wv = ((const unsigned*)p)[(size_t)lane * (size_t)((n / 4) / 32)];
        const int      ov = ((const int*)p)[2 * lane + 1];

        unsigned v = 0;
        if (bv > 1)                        v |= 1;   // byte-bool violated
        if (wv > 1u)                       v |= 2;   // word-int-bool violated
        if (wv != 0u && wv != 0x3F800000u) v |= 4;   // word-float-bool violated
        if (ov != 0)                       v |= 8;   // odd-words-zero violated
        v = __reduce_or_sync(0xFFFFFFFFu, v);

        if (lane == 0) {
            // mask buffer iff some bool interpretation has zero violations
            s_isMask[w] = (!(v & 2)) || (!(v & 4)) || (!(v & 1));
            s_odd[w]    = (v & 8) ? 1 : 0;
            s_wide[w]   = ((!(v & 2)) || (!(v & 4))) ? 1 : 0;   // 4-byte bool
        }
    }
    __syncthreads();

    if (threadIdx.x == 0) {
        for (int k = 0; k < 3; k++) {
            const int A = 2 * k, B = 2 * k + 1;
            const int swap = (s_isMask[A] && !s_isMask[B]) ? 1 : 0;
            const int idsI = swap ? B : A;
            const int mI   = swap ? A : B;
            g_cfg[k]     = swap;
            g_cfg[3 + k] = s_odd[idsI] ? 1 : 2;   // odd words all zero => int64
            g_cfg[6 + k] = s_wide[mI] ? 4 : 1;
        }
        g_cfg[9] = s_wide[6] ? 4 : 1;
    }
}

__device__ __forceinline__ int read_mask(const unsigned char* m, int idx, int w) {
    return (w == 4) ? (((const int*)m)[idx] != 0) : (m[idx] != 0);
}

__global__ __launch_bounds__(128, 16) void patch_embed_kernel(
    const unsigned char* __restrict__ a1, const unsigned char* __restrict__ b1,
    const unsigned char* __restrict__ a2, const unsigned char* __restrict__ b2,
    const unsigned char* __restrict__ a3, const unsigned char* __restrict__ b3,
    const unsigned char* __restrict__ pmask,
    const float4* __restrict__ e1,
    const float4* __restrict__ e2,
    const float4* __restrict__ e3,
    float4* __restrict__ out)
{
    __shared__ const float4* ptrs[LTOT];

    const int patch = blockIdx.x;   // 0..8191
    const int t = threadIdx.x;      // 0..127

    // ---- stage row pointers (masked -> nullptr) ----
    if (t < LTOT) {
        const float4* p = nullptr;
        if (read_mask(pmask, patch, g_cfg[9])) {
            int k, j, nk;
            const unsigned char *pa, *pb;
            const float4* e;
            if (t < L1N)            { k = 0; j = t;             nk = L1N; pa = a1; pb = b1; e = e1; }
            else if (t < L1N + L2N) { k = 1; j = t - L1N;       nk = L2N; pa = a2; pb = b2; e = e2; }
            else                    { k = 2; j = t - L1N - L2N; nk = L3N; pa = a3; pb = b3; e = e3; }

            const int swap = g_cfg[k];
            const int st   = g_cfg[3 + k];
            const int wm   = g_cfg[6 + k];
            const unsigned char* ids = swap ? pb : pa;
            const unsigned char* msk = swap ? pa : pb;
            const int idx = patch * nk + j;
            if (read_mask(msk, idx, wm)) {
                const unsigned id = (unsigned)((const int*)ids)[idx * st] & 0xFFFFu;
                p = e + (size_t)id * DV;
            }
        }
        ptrs[t] = p;
    }
    __syncthreads();

    // ---- gather + sum (coalesced: 128 threads x float4 = one 2KB row) ----
    float4 acc = make_float4(0.f, 0.f, 0.f, 0.f);
#pragma unroll
    for (int i = 0; i < LTOT; i++) {
        const float4* p = ptrs[i];       // warp-uniform branch
        if (p) {
            const float4 v = __ldg(p + t);
            acc.x += v.x; acc.y += v.y; acc.z += v.z; acc.w += v.w;
        }
    }
    // Evict-first store: never-re-read output must not displace rows in L2.
    __stcs(&out[(size_t)patch * DV + t], acc);
}

extern "C" void kernel_launch(void* const* d_in, const int* in_sizes, int n_in,
                              void* d_out, int out_size)
{
    const unsigned char *a1 = nullptr, *b1 = nullptr;
    const unsigned char *a2 = nullptr, *b2 = nullptr;
    const unsigned char *a3 = nullptr, *b3 = nullptr;
    const unsigned char *pm = nullptr;
    const float4* emb[3] = {nullptr, nullptr, nullptr};
    int ne = 0;

    for (int i = 0; i < n_in; i++) {
        const int sz = in_sizes[i];
        const unsigned char* p = (const unsigned char*)d_in[i];
        switch (sz) {
            case 33554432: if (ne < 3) emb[ne++] = (const float4*)p; break;
            case 8192:     pm = p; break;
            case 65536:    if (!a1) a1 = p; else b1 = p; break;
            case 57344:    if (!a2) a2 = p; else b2 = p; break;
            case 49152:    if (!a3) a3 = p; else b3 = p; break;
            default: break;
        }
    }

    probe_kernel<<<1, 224>>>(a1, b1, a2, b2, a3, b3, pm);
    patch_embed_kernel<<<NPATCH, 128>>>(a1, b1, a2, b2, a3, b3, pm,
                                        emb[0], emb[1], emb[2],
                                        (float4*)d_out);
}